// round 10
// baseline (speedup 1.0000x reference)
#include <cuda_runtime.h>
#include <cooperative_groups.h>

namespace cg = cooperative_groups;

// FPS, torch_geometric semantics. 16 clouds x 16384 -> 4096 samples/cloud.
// TWO clouds per 4-CTA cluster (8 clusters, 32 CTAs): interleaving hides the
// serial reduce/exchange tail of one cloud behind the other cloud's update.
// Exchange: DSMEM slot records + mbarrier release/acquire, lane0-per-warp wait.
// Bit-exact arithmetic (validated R6/R8): d = (dx*dx+dy*dy)+dz*dz, RN, no FMA
// contraction, sub = add of negated. argmax = first occurrence (lowest index).
// Output: float32 values of global indices.

#define N_CLOUDS 16
#define PTS      16384
#define M_SAMP   4096
#define THREADS  512
#define CL       4
#define QTR      4096    // points per CTA per cloud
#define PAIRS    4       // 8 pts/thread/cloud = 4 f32x2 pairs

__device__ __forceinline__ unsigned long long pack2(float lo, float hi) {
    unsigned long long r;
    asm("mov.b64 %0, {%1, %2};" : "=l"(r) : "f"(lo), "f"(hi));
    return r;
}
__device__ __forceinline__ void unpack2(unsigned long long v, float& lo, float& hi) {
    asm("mov.b64 {%0, %1}, %2;" : "=f"(lo), "=f"(hi) : "l"(v));
}
__device__ __forceinline__ unsigned long long add2(unsigned long long a, unsigned long long b) {
    unsigned long long r;
    asm("add.rn.f32x2 %0, %1, %2;" : "=l"(r) : "l"(a), "l"(b));
    return r;
}
__device__ __forceinline__ unsigned long long mul2(unsigned long long a, unsigned long long b) {
    unsigned long long r;
    asm("mul.rn.f32x2 %0, %1, %2;" : "=l"(r) : "l"(a), "l"(b));
    return r;
}
__device__ __forceinline__ unsigned int smem_u32(const void* p) {
    unsigned int a;
    asm("{ .reg .u64 t; cvta.to.shared.u64 t, %1; cvt.u32.u64 %0, t; }" : "=r"(a) : "l"(p));
    return a;
}
__device__ __forceinline__ unsigned int mapa_u32(unsigned int local_addr, unsigned int peer) {
    unsigned int r;
    asm("mapa.shared::cluster.u32 %0, %1, %2;" : "=r"(r) : "r"(local_addr), "r"(peer));
    return r;
}

// Per-cloud min-dist update + local argmax. Bit-exact chain (do not touch).
__device__ __forceinline__ void update_cloud(
    const unsigned long long (&CX)[PAIRS], const unsigned long long (&CY)[PAIRS],
    const unsigned long long (&CZ)[PAIRS], float (&d)[2 * PAIRS],
    float sx, float sy, float sz, float& best, int& jj)
{
    const unsigned long long nx2 = pack2(-sx, -sx);
    const unsigned long long ny2 = pack2(-sy, -sy);
    const unsigned long long nz2 = pack2(-sz, -sz);
    best = 0.0f; jj = 0;
#pragma unroll
    for (int pr = 0; pr < PAIRS; ++pr) {
        unsigned long long dx = add2(CX[pr], nx2);
        unsigned long long dy = add2(CY[pr], ny2);
        unsigned long long dz = add2(CZ[pr], nz2);
        unsigned long long s  = add2(add2(mul2(dx, dx), mul2(dy, dy)), mul2(dz, dz));
        float lo, hi;
        unpack2(s, lo, hi);
        {
            float nd = fminf(d[2 * pr], lo);
            d[2 * pr] = nd;
            bool c = nd > best; best = c ? nd : best; jj = c ? 2 * pr : jj;
        }
        {
            float nd = fminf(d[2 * pr + 1], hi);
            d[2 * pr + 1] = nd;
            bool c = nd > best; best = c ? nd : best; jj = c ? 2 * pr + 1 : jj;
        }
    }
}

__device__ __forceinline__ unsigned long long warp_max(unsigned long long key) {
#pragma unroll
    for (int off = 16; off > 0; off >>= 1) {
        unsigned long long o = __shfl_xor_sync(0xFFFFFFFFu, key, off);
        if (o > key) key = o;
    }
    return key;
}

// Owner publish: write {key, xy, z} to this slot in ALL 4 CTAs (incl. self via
// loopback), then arrive (release) on all 4 mbars. count=4 per phase.
__device__ __forceinline__ void publish(
    unsigned int slot_a, unsigned int mbar_a, unsigned rank,
    unsigned long long key, float wx, float wy, float wz)
{
    const unsigned long long xy = pack2(wx, wy);
    const unsigned long long zz = pack2(wz, 0.0f);
#pragma unroll
    for (unsigned r = 0; r < CL; ++r) {
        const unsigned int rs = mapa_u32(slot_a, r);
        asm volatile("st.shared::cluster.b64 [%0],    %1;" :: "r"(rs), "l"(key) : "memory");
        asm volatile("st.shared::cluster.b64 [%0+8],  %1;" :: "r"(rs), "l"(xy)  : "memory");
        asm volatile("st.shared::cluster.b64 [%0+16], %1;" :: "r"(rs), "l"(zz)  : "memory");
    }
#pragma unroll
    for (unsigned r = 0; r < CL; ++r) {
        const unsigned int rm = mapa_u32(mbar_a, r);
        asm volatile("mbarrier.arrive.release.cluster.shared::cluster.b64 _, [%0];"
                     :: "r"(rm) : "memory");
    }
}

__device__ __forceinline__ void wait_phase(unsigned int mbar_a, unsigned int parity, int lane) {
    if (lane == 0) {
        asm volatile(
            "{\n\t.reg .pred P;\n"
            "W%=:\n\tmbarrier.try_wait.parity.acquire.cluster.shared::cta.b64 P, [%0], %1, 2000;\n"
            "\t@!P bra W%=;\n\t}"
            :: "r"(mbar_a), "r"(parity) : "memory");
    }
    __syncwarp(0xFFFFFFFFu);
}

__global__ __launch_bounds__(THREADS, 1) __cluster_dims__(CL, 1, 1)
void fps_kernel(const float* __restrict__ pos, float* __restrict__ out)
{
    __shared__ unsigned long long skA[2][16], skB[2][16];          // parity-buffered warp keys
    __shared__ unsigned long long slotsA[2][CL][3], slotsB[2][CL][3]; // [par][rank]{key,xy,z}
    __shared__ unsigned long long mbarA, mbarB;

    cg::cluster_group cluster = cg::this_cluster();
    const unsigned rank = cluster.block_rank();
    const int cid  = blockIdx.x >> 2;              // cluster id = cloud pair
    const int cA   = 2 * cid, cB = 2 * cid + 1;
    const int base = (int)rank * QTR;

    const int t    = threadIdx.x;
    const int lane = t & 31;
    const int wid  = t >> 5;
    const float* pA = pos + (size_t)cA * PTS * 3;
    const float* pB = pos + (size_t)cB * PTS * 3;

    const unsigned int mbarA_a = smem_u32(&mbarA);
    const unsigned int mbarB_a = smem_u32(&mbarB);

    if (t == 0) {
        asm volatile("mbarrier.init.shared.b64 [%0], %1;" :: "r"(mbarA_a), "r"(CL) : "memory");
        asm volatile("mbarrier.init.shared.b64 [%0], %1;" :: "r"(mbarB_a), "r"(CL) : "memory");
    }

    unsigned long long AX[PAIRS], AY[PAIRS], AZ[PAIRS];
    unsigned long long BX[PAIRS], BY[PAIRS], BZ[PAIRS];
    float dA[2 * PAIRS], dB[2 * PAIRS];
    const float INF = __int_as_float(0x7f800000);

#pragma unroll
    for (int pr = 0; pr < PAIRS; ++pr) {
        int g0 = base + t + ((2 * pr)     << 9);
        int g1 = base + t + ((2 * pr + 1) << 9);
        AX[pr] = pack2(pA[3 * g0 + 0], pA[3 * g1 + 0]);
        AY[pr] = pack2(pA[3 * g0 + 1], pA[3 * g1 + 1]);
        AZ[pr] = pack2(pA[3 * g0 + 2], pA[3 * g1 + 2]);
        BX[pr] = pack2(pB[3 * g0 + 0], pB[3 * g1 + 0]);
        BY[pr] = pack2(pB[3 * g0 + 1], pB[3 * g1 + 1]);
        BZ[pr] = pack2(pB[3 * g0 + 2], pB[3 * g1 + 2]);
        dA[2 * pr] = INF; dA[2 * pr + 1] = INF;
        dB[2 * pr] = INF; dB[2 * pr + 1] = INF;
    }

    float sxA = pA[0], syA = pA[1], szA = pA[2];
    float sxB = pB[0], syB = pB[1], szB = pB[2];
    if (t == 0 && rank == 0) {
        out[cA * M_SAMP] = (float)(cA * PTS);
        out[cB * M_SAMP] = (float)(cB * PTS);
    }

    cluster.sync();   // mbar init visible cluster-wide before any arrive

    for (int i = 1; i < M_SAMP; ++i) {
        const int par = i & 1;
        const unsigned int parity = (unsigned)((i - 1) & 1);

        // ---- both updates (bulk of issue work) ----
        float bestA, bestB; int jjA, jjB;
        update_cloud(AX, AY, AZ, dA, sxA, syA, szA, bestA, jjA);
        update_cloud(BX, BY, BZ, dB, sxB, syB, szB, bestB, jjB);

        const unsigned int giA = (unsigned int)(base + t) + ((unsigned int)jjA << 9);
        const unsigned long long mykeyA =
            ((unsigned long long)__float_as_uint(bestA) << 32) |
            (unsigned long long)(0xFFFFFFFFu - giA);
        const unsigned int giB = (unsigned int)(base + t) + ((unsigned int)jjB << 9);
        const unsigned long long mykeyB =
            ((unsigned long long)__float_as_uint(bestB) << 32) |
            (unsigned long long)(0xFFFFFFFFu - giB);

        unsigned long long wkA = warp_max(mykeyA);
        unsigned long long wkB = warp_max(mykeyB);
        if (lane == 0) { skA[par][wid] = wkA; skB[par][wid] = wkB; }
        __syncthreads();   // the ONE barrier per iteration

        // ---- A: scan + publish ----
        unsigned long long kbA = skA[par][0];
#pragma unroll
        for (int w = 1; w < 16; ++w) { unsigned long long o = skA[par][w]; if (o > kbA) kbA = o; }
        if (mykeyA == kbA) {
            const int prw = jjA >> 1, hw = jjA & 1;
            float wx = 0.f, wy = 0.f, wz = 0.f;
#pragma unroll
            for (int pr = 0; pr < PAIRS; ++pr) {
                if (pr == prw) {
                    float l0, h0, l1, h1, l2, h2;
                    unpack2(AX[pr], l0, h0); unpack2(AY[pr], l1, h1); unpack2(AZ[pr], l2, h2);
                    wx = hw ? h0 : l0; wy = hw ? h1 : l1; wz = hw ? h2 : l2;
                }
            }
            publish(smem_u32(&slotsA[par][rank][0]), mbarA_a, rank, kbA, wx, wy, wz);
        }

        // ---- B: scan + publish ----
        unsigned long long kbB = skB[par][0];
#pragma unroll
        for (int w = 1; w < 16; ++w) { unsigned long long o = skB[par][w]; if (o > kbB) kbB = o; }
        if (mykeyB == kbB) {
            const int prw = jjB >> 1, hw = jjB & 1;
            float wx = 0.f, wy = 0.f, wz = 0.f;
#pragma unroll
            for (int pr = 0; pr < PAIRS; ++pr) {
                if (pr == prw) {
                    float l0, h0, l1, h1, l2, h2;
                    unpack2(BX[pr], l0, h0); unpack2(BY[pr], l1, h1); unpack2(BZ[pr], l2, h2);
                    wx = hw ? h0 : l0; wy = hw ? h1 : l1; wz = hw ? h2 : l2;
                }
            }
            publish(smem_u32(&slotsB[par][rank][0]), mbarB_a, rank, kbB, wx, wy, wz);
        }

        // ---- wait + combine A (latency hidden behind B's scan/publish) ----
        wait_phase(mbarA_a, parity, lane);
        {
            unsigned long long gk = slotsA[par][0][0]; int wi = 0;
#pragma unroll
            for (int w = 1; w < CL; ++w) {
                unsigned long long o = slotsA[par][w][0];
                if (o > gk) { gk = o; wi = w; }
            }
            float zlo, zhi;
            unpack2(slotsA[par][wi][1], sxA, syA);
            unpack2(slotsA[par][wi][2], zlo, zhi);
            szA = zlo;
            if (t == 0 && rank == 0) {
                const unsigned int gw = 0xFFFFFFFFu - (unsigned int)gk;
                out[cA * M_SAMP + i] = (float)(cA * PTS + (int)gw);
            }
        }

        // ---- wait + combine B ----
        wait_phase(mbarB_a, parity, lane);
        {
            unsigned long long gk = slotsB[par][0][0]; int wi = 0;
#pragma unroll
            for (int w = 1; w < CL; ++w) {
                unsigned long long o = slotsB[par][w][0];
                if (o > gk) { gk = o; wi = w; }
            }
            float zlo, zhi;
            unpack2(slotsB[par][wi][1], sxB, syB);
            unpack2(slotsB[par][wi][2], zlo, zhi);
            szB = zlo;
            if (t == 0 && rank == 0) {
                const unsigned int gw = 0xFFFFFFFFu - (unsigned int)gk;
                out[cB * M_SAMP + i] = (float)(cB * PTS + (int)gw);
            }
        }
    }
}

extern "C" void kernel_launch(void* const* d_in, const int* in_sizes, int n_in,
                              void* d_out, int out_size)
{
    // Resolve pos BY SIZE (786432 floats), robust to input ordering.
    const float* pos = nullptr;
    for (int i = 0; i < n_in; ++i) {
        if (in_sizes[i] == N_CLOUDS * PTS * 3) { pos = (const float*)d_in[i]; break; }
    }
    if (!pos) pos = (const float*)d_in[0];

    float* out = (float*)d_out;   // [N_CLOUDS*M_SAMP] float32 index values

    fps_kernel<<<(N_CLOUDS / 2) * CL, THREADS>>>(pos, out);
}

// round 11
// speedup vs baseline: 4.8046x; 4.8046x over previous
#include <cuda_runtime.h>
#include <cooperative_groups.h>

namespace cg = cooperative_groups;

// FPS, torch_geometric semantics. 16 clouds x 16384 -> 4096 samples/cloud.
// 4-CTA cluster per cloud (64 CTAs), 4096 points per CTA, min-dists in regs.
// Cross-CTA exchange: R8's PROVEN protocol — DSMEM slot stores + cluster.sync
// (mbarrier handshake measured catastrophically slow in R9/R10; reverted).
// Bit-exact arithmetic (validated R6/R8): d = (dx*dx+dy*dy)+dz*dz, RN, no FMA
// contraction, sub = add of negated. argmax = first occurrence (lowest index).
// Output: float32 values of global indices.

#define N_CLOUDS 16
#define PTS      16384
#define M_SAMP   4096
#define THREADS  512
#define CL       4
#define QTR      4096    // points per CTA
#define PAIRS    4       // 8 points per thread = 4 f32x2 pairs

__device__ __forceinline__ unsigned long long pack2(float lo, float hi) {
    unsigned long long r;
    asm("mov.b64 %0, {%1, %2};" : "=l"(r) : "f"(lo), "f"(hi));
    return r;
}
__device__ __forceinline__ void unpack2(unsigned long long v, float& lo, float& hi) {
    asm("mov.b64 {%0, %1}, %2;" : "=f"(lo), "=f"(hi) : "l"(v));
}
// Packed IEEE RN f32x2 ops (sm_100+): bit-identical to scalar FADD/FMUL.
__device__ __forceinline__ unsigned long long add2(unsigned long long a, unsigned long long b) {
    unsigned long long r;
    asm("add.rn.f32x2 %0, %1, %2;" : "=l"(r) : "l"(a), "l"(b));
    return r;
}
__device__ __forceinline__ unsigned long long mul2(unsigned long long a, unsigned long long b) {
    unsigned long long r;
    asm("mul.rn.f32x2 %0, %1, %2;" : "=l"(r) : "l"(a), "l"(b));
    return r;
}

struct __align__(8) Slot { unsigned long long key; float x, y, z; };

__global__ __launch_bounds__(THREADS, 1) __cluster_dims__(CL, 1, 1)
void fps_kernel(const float* __restrict__ pos, float* __restrict__ out)
{
    __shared__ unsigned long long skeys[16];   // per-warp reduced keys
    __shared__ Slot slots[2][CL];              // [parity][rank] exchange records

    cg::cluster_group cluster = cg::this_cluster();
    const unsigned rank = cluster.block_rank();          // 0..3
    const int b    = blockIdx.x >> 2;                    // cloud id
    const int base = (int)rank * QTR;                    // cloud-local CTA offset

    const int t    = threadIdx.x;
    const int lane = t & 31;
    const int wid  = t >> 5;
    const float* p = pos + (size_t)b * PTS * 3;

    // This thread's 8 points: cloud-local index g = base + t + (k<<9), k=0..7.
    unsigned long long CX[PAIRS], CY[PAIRS], CZ[PAIRS];
    float d[2 * PAIRS];
    const float INF = __int_as_float(0x7f800000);

#pragma unroll
    for (int pr = 0; pr < PAIRS; ++pr) {
        int g0 = base + t + ((2 * pr)     << 9);
        int g1 = base + t + ((2 * pr + 1) << 9);
        float x0 = p[3 * g0 + 0], y0 = p[3 * g0 + 1], z0 = p[3 * g0 + 2];
        float x1 = p[3 * g1 + 0], y1 = p[3 * g1 + 1], z1 = p[3 * g1 + 2];
        CX[pr] = pack2(x0, x1);
        CY[pr] = pack2(y0, y1);
        CZ[pr] = pack2(z0, z1);
        d[2 * pr]     = INF;
        d[2 * pr + 1] = INF;
    }

    // First pick: cloud-local index 0 (L1-broadcast load by all threads).
    float sx = p[0], sy = p[1], sz = p[2];
    if (t == 0 && rank == 0) out[b * M_SAMP] = (float)(b * PTS);

    // Both sides of the per-iteration protocol alive.
    cluster.sync();

    for (int i = 1; i < M_SAMP; ++i) {
        const unsigned long long nx2 = pack2(-sx, -sx);
        const unsigned long long ny2 = pack2(-sy, -sy);
        const unsigned long long nz2 = pack2(-sz, -sz);

        float best = 0.0f;
        int jj = 0;

#pragma unroll
        for (int pr = 0; pr < PAIRS; ++pr) {
            unsigned long long dx = add2(CX[pr], nx2);       // exact sub
            unsigned long long dy = add2(CY[pr], ny2);
            unsigned long long dz = add2(CZ[pr], nz2);
            unsigned long long s  = add2(add2(mul2(dx, dx), mul2(dy, dy)), mul2(dz, dz));
            float lo, hi;
            unpack2(s, lo, hi);
            {
                float nd = fminf(d[2 * pr], lo);
                d[2 * pr] = nd;
                bool c = nd > best; best = c ? nd : best; jj = c ? 2 * pr : jj;
            }
            {
                float nd = fminf(d[2 * pr + 1], hi);
                d[2 * pr + 1] = nd;
                bool c = nd > best; best = c ? nd : best; jj = c ? 2 * pr + 1 : jj;
            }
        }

        // u64 key: high = dist bits, low = ~cloud_local_idx (lowest-index ties).
        const unsigned int gidx = (unsigned int)(base + t) + ((unsigned int)jj << 9);
        const unsigned long long mykey =
            ((unsigned long long)__float_as_uint(best) << 32) |
            (unsigned long long)(0xFFFFFFFFu - gidx);

        unsigned long long key = mykey;
#pragma unroll
        for (int off = 16; off > 0; off >>= 1) {
            unsigned long long o = __shfl_xor_sync(0xFFFFFFFFu, key, off);
            if (o > key) key = o;
        }
        if (lane == 0) skeys[wid] = key;
        __syncthreads();                                   // (A)

        unsigned long long kbest = skeys[0];
#pragma unroll
        for (int w = 1; w < 16; ++w) {
            unsigned long long o = skeys[w];
            if (o > kbest) kbest = o;
        }

        const int par = i & 1;

        // UNIQUE owner (pre-reduction key == CTA max) publishes {key, coords}
        // to its slot in ALL CTAs (local + 3 peers via DSMEM).
        if (mykey == kbest) {
            const int prw = jj >> 1;
            const int hw  = jj & 1;
            float wx = 0.f, wy = 0.f, wz = 0.f;
#pragma unroll
            for (int pr = 0; pr < PAIRS; ++pr) {
                if (pr == prw) {
                    float l0, h0, l1, h1, l2, h2;
                    unpack2(CX[pr], l0, h0);
                    unpack2(CY[pr], l1, h1);
                    unpack2(CZ[pr], l2, h2);
                    wx = hw ? h0 : l0;
                    wy = hw ? h1 : l1;
                    wz = hw ? h2 : l2;
                }
            }
            // Local record
            slots[par][rank].key = kbest;
            slots[par][rank].x = wx;
            slots[par][rank].y = wy;
            slots[par][rank].z = wz;
            // Peer records via DSMEM (release/acquire provided by cluster.sync)
#pragma unroll
            for (unsigned pr_ = 1; pr_ < CL; ++pr_) {
                const unsigned peer = (rank + pr_) & (CL - 1);
                Slot* rs = cluster.map_shared_rank(&slots[par][rank], peer);
                rs->key = kbest;
                rs->x = wx; rs->y = wy; rs->z = wz;
            }
        }

        // Orders publishes before reads; also reuses as the second CTA barrier
        // (skeys and slots are parity-double-buffered).
        cluster.sync();

        const Slot* sp = slots[par];
        unsigned long long gk = sp[0].key;
        int wi = 0;
#pragma unroll
        for (int w = 1; w < CL; ++w) {
            unsigned long long o = sp[w].key;
            if (o > gk) { gk = o; wi = w; }
        }
        sx = sp[wi].x; sy = sp[wi].y; sz = sp[wi].z;

        if (t == 0 && rank == 0) {
            const unsigned int gw = 0xFFFFFFFFu - (unsigned int)gk;
            out[b * M_SAMP + i] = (float)(b * PTS + (int)gw);
        }
    }
}

extern "C" void kernel_launch(void* const* d_in, const int* in_sizes, int n_in,
                              void* d_out, int out_size)
{
    // Resolve pos BY SIZE (786432 floats), robust to input ordering.
    const float* pos = nullptr;
    for (int i = 0; i < n_in; ++i) {
        if (in_sizes[i] == N_CLOUDS * PTS * 3) { pos = (const float*)d_in[i]; break; }
    }
    if (!pos) pos = (const float*)d_in[0];

    float* out = (float*)d_out;   // [N_CLOUDS*M_SAMP] float32 index values

    fps_kernel<<<N_CLOUDS * CL, THREADS>>>(pos, out);
}